// round 1
// baseline (speedup 1.0000x reference)
#include <cuda_runtime.h>
#include <math.h>

#define T    128
#define D    64
#define H    256
#define HK   128
#define DD   (D*D)
#define ITERS 3
#define NPART 256   // kG grid: 128 j-blocks x 2 h-halves

// ---- scratch (static device globals; no runtime allocation) ----
__device__ float A_g[T*T*HK];          // 8 MB  A[i][j*HK+h] = w_ij * tanh(...)
__device__ float fy_g[T*D];            //       f(y)
__device__ float c_g[T*D];             //       bias projection bk2 . f(y)
__device__ float M3_g[T*HK*D];         // 4 MB  M3[(j*HK+h)][d]
__device__ float Gpart_g[NPART*T*D];   // 8 MB  split-K partials (deterministic)
__device__ float G_g[T*D];
__device__ float Y_g[T*D];

// trapezoid weight w[i][j] on uniform grid, matching the reference exactly:
// w = dt * (j<=i); w[i,i]*=0.5; w[:,0]*=0.5; w[0,:]=0
__device__ __forceinline__ float wfun(int i, int j, float dt) {
    if (i == 0 || j > i) return 0.0f;
    float v = dt;
    if (j == i) v *= 0.5f;
    if (j == 0) v *= 0.5f;
    return v;
}

// ---------------- init: Y = tile(y0) ----------------
__global__ void kInit(const float* __restrict__ z0) {
    int idx = blockIdx.x * 256 + threadIdx.x;      // 8192
    Y_g[idx] = z0[idx & (D - 1)];
}

// ------- precompute A[i][j*HK+h] = w_ij * tanh(t_i*Wk1[0,h] + t_j*Wk1[1,h] + bk1[h]) -------
__global__ void kA(const float* __restrict__ t, const float* __restrict__ Wk1,
                   const float* __restrict__ bk1) {
    int bid = blockIdx.x;          // 16384 blocks
    int i = bid >> 7;
    int j = bid & 127;
    int h = threadIdx.x;           // 128 threads
    float dt = t[1] - t[0];
    float v = tanhf(t[i] * Wk1[h] + t[j] * Wk1[HK + h] + bk1[h]);
    A_g[i * (T * HK) + j * HK + h] = wfun(i, j, dt) * v;
}

// ------- f(y) = tanh(y W1 + b1) W2 + b2 ; and c = f(y) . bk2^T (per row) -------
__global__ void kF(const float* __restrict__ W1, const float* __restrict__ b1,
                   const float* __restrict__ W2, const float* __restrict__ b2,
                   const float* __restrict__ bk2) {
    __shared__ float yrow[D];
    __shared__ float hid[H];
    __shared__ float fyr[D];
    int j = blockIdx.x;            // 128 blocks
    int tid = threadIdx.x;         // 256 threads
    if (tid < D) yrow[tid] = Y_g[j * D + tid];
    __syncthreads();
    {
        float s = b1[tid];
        #pragma unroll
        for (int e = 0; e < D; e++) s += yrow[e] * W1[e * H + tid];   // coalesced in h
        hid[tid] = tanhf(s);
    }
    __syncthreads();
    if (tid < D) {
        float s = b2[tid];
        #pragma unroll 8
        for (int h = 0; h < H; h++) s += hid[h] * W2[h * D + tid];    // coalesced in d
        fy_g[j * D + tid] = s;
        fyr[tid] = s;
    }
    __syncthreads();
    if (tid < D) {
        float s = 0.0f;
        #pragma unroll 8
        for (int e = 0; e < D; e++) s += bk2[tid * D + e] * fyr[e];
        c_g[j * D + tid] = s;
    }
}

// ------- M3[(j*HK+h)][d] = sum_e Wk2[h, d*D+e] * fy[j,e] -------
// block = (h, 16-wide j-tile). Wk2 row staged transposed [e][d] with pad 65.
__global__ void kM3(const float* __restrict__ Wk2) {
    __shared__ float w2s[D * 65];      // [e][d], padded stride 65 (conflict-free)
    __shared__ float fys[16 * D];      // [j_local][e]
    int h  = blockIdx.x >> 3;          // 128
    int jt = blockIdx.x & 7;           // 8 tiles of 16 j
    int tid = threadIdx.x;             // 256
    #pragma unroll
    for (int r = 0; r < 16; r++) {
        int idx = tid + r * 256;                 // 4096 elems of row h
        float v = Wk2[h * DD + idx];
        int d = idx >> 6, e = idx & 63;
        w2s[e * 65 + d] = v;
    }
    #pragma unroll
    for (int r = 0; r < 4; r++) {
        int idx = tid + r * 256;                 // 1024 contiguous floats
        fys[idx] = fy_g[jt * 16 * D + idx];
    }
    __syncthreads();
    int d = tid & 63;
    int jq = tid >> 6;
    #pragma unroll
    for (int jl = jq; jl < 16; jl += 4) {
        float s = 0.0f;
        #pragma unroll
        for (int e = 0; e < D; e++) s += w2s[e * 65 + d] * fys[jl * D + e];
        int j = jt * 16 + jl;
        M3_g[(j * HK + h) * D + d] = s;          // coalesced in d
    }
}

// ------- split-K GEMM: Gpart[b][i][d] = sum_{h in half} A[i][j*HK+h] * M3[(j,h)][d] -------
// block b = (j, half). 256 threads, 8x4 register microtile per thread.
// Triangular skip: rows i<j contribute 0 (A zero) -> warps fully below j skip FMAs.
__global__ void kG() {
    __shared__ float As[16][T];    // [hh][i]
    __shared__ float Bs[16][D];    // [hh][d]
    int j    = blockIdx.x >> 1;
    int half = blockIdx.x & 1;
    int tid  = threadIdx.x;
    int tx = tid & 15;             // d-tile:  cols tx*4 .. tx*4+3
    int ty = tid >> 4;             // i-tile:  rows ty*8 .. ty*8+7
    float acc[8][4] = {};
    bool active = (ty * 8 + 7) >= j;
    int jbase = j * HK + half * 64;
    int iload = tid >> 1;          // 0..127
    int g = tid & 1;               // which 8-float chunk of the 16-h slice
    #pragma unroll
    for (int kb = 0; kb < 4; kb++) {
        const float* ap = &A_g[iload * (T * HK) + jbase + kb * 16 + g * 8];
        float4 v0 = *(const float4*)ap;
        float4 v1 = *(const float4*)(ap + 4);
        As[g * 8 + 0][iload] = v0.x;  As[g * 8 + 1][iload] = v0.y;
        As[g * 8 + 2][iload] = v0.z;  As[g * 8 + 3][iload] = v0.w;
        As[g * 8 + 4][iload] = v1.x;  As[g * 8 + 5][iload] = v1.y;
        As[g * 8 + 6][iload] = v1.z;  As[g * 8 + 7][iload] = v1.w;
        const float4* bp = (const float4*)&M3_g[(jbase + kb * 16) * D];
        ((float4*)Bs)[tid] = bp[tid];            // 1024 contiguous floats
        __syncthreads();
        if (active) {
            #pragma unroll
            for (int hh = 0; hh < 16; hh++) {
                float a[8], b[4];
                #pragma unroll
                for (int r = 0; r < 8; r++) a[r] = As[hh][ty * 8 + r];
                #pragma unroll
                for (int cc = 0; cc < 4; cc++) b[cc] = Bs[hh][tx * 4 + cc];
                #pragma unroll
                for (int r = 0; r < 8; r++)
                    #pragma unroll
                    for (int cc = 0; cc < 4; cc++)
                        acc[r][cc] += a[r] * b[cc];
            }
        }
        __syncthreads();
    }
    float* gp = &Gpart_g[blockIdx.x * (T * D)];
    #pragma unroll
    for (int r = 0; r < 8; r++)
        #pragma unroll
        for (int cc = 0; cc < 4; cc++)
            gp[(ty * 8 + r) * D + tx * 4 + cc] = acc[r][cc];
}

// ------- fixed-order reduction of partials + bias quadrature term -------
__global__ void kRed(const float* __restrict__ t) {
    int idx = blockIdx.x * 256 + threadIdx.x;    // 8192
    int i = idx >> 6, d = idx & 63;
    float acc = 0.0f;
    #pragma unroll 8
    for (int s = 0; s < NPART; s++) acc += Gpart_g[s * (T * D) + idx];
    if (i > 0) {
        float dt = t[1] - t[0];
        for (int j = 0; j <= i; j++) {
            float wv = dt;
            if (j == 0) wv *= 0.5f;
            if (j == i) wv *= 0.5f;
            acc += wv * c_g[j * D + d];
        }
    }
    G_g[idx] = acc;
}

// ------- y_new = y0 + w @ G ; write final output on last iteration -------
__global__ void kY(const float* __restrict__ t, const float* __restrict__ z0,
                   float* __restrict__ out, int last) {
    int idx = blockIdx.x * 256 + threadIdx.x;    // 8192
    int k = idx >> 6, d = idx & 63;
    float y = z0[d];
    if (k > 0) {
        float dt = t[1] - t[0];
        for (int i = 0; i <= k; i++) {
            float wv = dt;
            if (i == 0) wv *= 0.5f;
            if (i == k) wv *= 0.5f;
            y += wv * G_g[i * D + d];
        }
    }
    Y_g[idx] = y;
    if (last && k == T - 1) out[d] = y;
}

extern "C" void kernel_launch(void* const* d_in, const int* in_sizes, int n_in,
                              void* d_out, int out_size) {
    const float* z0  = (const float*)d_in[0];
    const float* t   = (const float*)d_in[1];
    const float* W1  = (const float*)d_in[2];
    const float* b1  = (const float*)d_in[3];
    const float* W2  = (const float*)d_in[4];
    const float* b2  = (const float*)d_in[5];
    const float* Wk1 = (const float*)d_in[6];
    const float* bk1 = (const float*)d_in[7];
    const float* Wk2 = (const float*)d_in[8];
    const float* bk2 = (const float*)d_in[9];
    float* out = (float*)d_out;

    kInit<<<32, 256>>>(z0);
    kA<<<T * T, HK>>>(t, Wk1, bk1);
    for (int it = 0; it < ITERS; it++) {
        kF<<<T, 256>>>(W1, b1, W2, b2, bk2);
        kM3<<<HK * 8, 256>>>(Wk2);
        kG<<<NPART, 256>>>();
        kRed<<<32, 256>>>(t);
        kY<<<32, 256>>>(t, z0, out, (it == ITERS - 1) ? 1 : 0);
    }
}

// round 2
// speedup vs baseline: 1.3084x; 1.3084x over previous
#include <cuda_runtime.h>
#include <math.h>

#define T    128
#define D    64
#define H    256
#define HK   128
#define DD   (D*D)
#define ITERS 3
#define NPART 256   // kG grid: 128 j-blocks x 2 h-halves

// ---- scratch (static device globals; no runtime allocation) ----
__device__ float A_g[T*T*HK];          // 8 MB  A[i][j*HK+h] = w_ij * tanh(...)
__device__ float W2T_g[HK*DD];         // 2 MB  Wk2 transposed per-row: [h][e][d]
__device__ float fy_g[T*D];            //       f(y)
__device__ float c_g[T*D];             //       bias projection bk2 . f(y)
__device__ float M3_g[T*HK*D];         // 4 MB  M3[(j*HK+h)][d]
__device__ float Gpart_g[NPART*T*D];   // 8 MB  split-K partials (deterministic)
__device__ float G_g[T*D];
__device__ float Y_g[T*D];

// trapezoid weight w[i][j]: w = dt*(j<=i); w[i,i]*=0.5; w[:,0]*=0.5; w[0,:]=0
__device__ __forceinline__ float wfun(int i, int j, float dt) {
    if (i == 0 || j > i) return 0.0f;
    float v = dt;
    if (j == i) v *= 0.5f;
    if (j == 0) v *= 0.5f;
    return v;
}

// ---------------- init: Y = tile(y0) ----------------
__global__ void kInit(const float* __restrict__ z0) {
    int idx = blockIdx.x * 256 + threadIdx.x;      // 8192
    Y_g[idx] = z0[idx & (D - 1)];
}

// ------- A[i][j*HK+h] = w_ij * tanh(t_i*Wk1[0,h] + t_j*Wk1[1,h] + bk1[h]) -------
// 128 blocks (one per i), 256 threads, params staged in smem.
__global__ void kA(const float* __restrict__ t, const float* __restrict__ Wk1,
                   const float* __restrict__ bk1) {
    __shared__ float wa[HK], wb[HK], bk[HK], ts[T];
    int tid = threadIdx.x;
    int i = blockIdx.x;
    if (tid < HK) { wa[tid] = Wk1[tid]; wb[tid] = Wk1[HK + tid]; bk[tid] = bk1[tid]; }
    if (tid < T)  ts[tid] = t[tid];
    __syncthreads();
    float ti = ts[i];
    float dt = ts[1] - ts[0];
    #pragma unroll 4
    for (int r = 0; r < 64; r++) {
        int idx = tid + r * 256;                  // 0..16383
        int j = idx >> 7, h = idx & 127;
        float v = tanhf(ti * wa[h] + ts[j] * wb[h] + bk[h]);
        A_g[i * (T * HK) + idx] = wfun(i, j, dt) * v;
    }
}

// ------- one-time transpose: W2T[h][e][d] = Wk2[h][d*64+e] -------
// smem tile with stride-67 padding: conflict-free both directions.
__global__ void kT(const float* __restrict__ Wk2) {
    __shared__ float sm[D * 67];
    int h = blockIdx.x;            // 128 blocks
    int tid = threadIdx.x;         // 256
    #pragma unroll
    for (int r = 0; r < 16; r++) {
        int idx = tid + r * 256;   // d = idx>>6, e = idx&63
        sm[(idx >> 6) * 67 + (idx & 63)] = Wk2[h * DD + idx];
    }
    __syncthreads();
    #pragma unroll
    for (int r = 0; r < 16; r++) {
        int idx = tid + r * 256;   // e = idx>>6, d = idx&63
        W2T_g[h * DD + idx] = sm[(idx & 63) * 67 + (idx >> 6)];
    }
}

// ------- f(y) = tanh(y W1 + b1) W2 + b2 ; c = f(y) . bk2 rows -------
__global__ void kF(const float* __restrict__ W1, const float* __restrict__ b1,
                   const float* __restrict__ W2, const float* __restrict__ b2,
                   const float* __restrict__ bk2) {
    __shared__ float yrow[D];
    __shared__ float hid[H];
    __shared__ float fyr[D];
    int j = blockIdx.x;            // 128 blocks
    int tid = threadIdx.x;         // 256 threads
    if (tid < D) yrow[tid] = Y_g[j * D + tid];
    __syncthreads();
    {
        float s = b1[tid];
        #pragma unroll
        for (int e = 0; e < D; e++) s += yrow[e] * W1[e * H + tid];
        hid[tid] = tanhf(s);
    }
    __syncthreads();
    if (tid < D) {
        float s = b2[tid];
        #pragma unroll 8
        for (int h = 0; h < H; h++) s += hid[h] * W2[h * D + tid];
        fy_g[j * D + tid] = s;
        fyr[tid] = s;
    }
    __syncthreads();
    if (tid < D) {
        float s = 0.0f;
        #pragma unroll 8
        for (int e = 0; e < D; e++) s += bk2[tid * D + e] * fyr[e];
        c_g[j * D + tid] = s;
    }
}

// ------- M3[(j*HK+h)][d] = sum_e W2T[h][e][d] * fy[j,e] -------
// block = (h, j-half of 64). Clean GEMM: float4 w reads, padded fys, 4x4 tiles.
__global__ void kM3() {
    __shared__ float w2s[D * D];       // [e][d] raw, conflict-free
    __shared__ float fys[D * 65];      // [j][e] padded
    int h  = blockIdx.x >> 1;          // 128
    int jh = blockIdx.x & 1;           // j half
    int tid = threadIdx.x;             // 256
    #pragma unroll
    for (int r = 0; r < 16; r++)
        w2s[tid + r * 256] = W2T_g[h * DD + tid + r * 256];
    #pragma unroll
    for (int r = 0; r < 16; r++) {
        int idx = tid + r * 256;       // j = idx>>6, e = idx&63
        fys[(idx >> 6) * 65 + (idx & 63)] = fy_g[jh * 64 * D + idx];
    }
    __syncthreads();
    int tx = tid & 15;                 // d-chunk: 4*tx
    int ty = tid >> 4;                 // j-chunk: 4*ty
    float acc[4][4] = {};
    #pragma unroll
    for (int e = 0; e < D; e++) {
        float4 wv = *(const float4*)&w2s[e * 64 + tx * 4];
        #pragma unroll
        for (int jl = 0; jl < 4; jl++) {
            float f = fys[(ty * 4 + jl) * 65 + e];
            acc[jl][0] += f * wv.x; acc[jl][1] += f * wv.y;
            acc[jl][2] += f * wv.z; acc[jl][3] += f * wv.w;
        }
    }
    #pragma unroll
    for (int jl = 0; jl < 4; jl++) {
        int j = jh * 64 + ty * 4 + jl;
        float4 o = make_float4(acc[jl][0], acc[jl][1], acc[jl][2], acc[jl][3]);
        *(float4*)&M3_g[(j * HK + h) * D + tx * 4] = o;
    }
}

// ------- split-K GEMM: Gpart[b][i][d] = sum_{h in half} A[i][j*HK+h] * M3[(j,h)][d] -------
__global__ void kG() {
    __shared__ float As[16][T];    // [hh][i]
    __shared__ float Bs[16][D];    // [hh][d]
    int j    = blockIdx.x >> 1;
    int half = blockIdx.x & 1;
    int tid  = threadIdx.x;
    int tx = tid & 15;             // d cols tx*4..+3
    int ty = tid >> 4;             // i rows ty*8..+7
    float acc[8][4] = {};
    bool active = (ty * 8 + 7) >= j;
    int jbase = j * HK + half * 64;
    int iload = tid >> 1;          // 0..127
    int g = tid & 1;
    #pragma unroll
    for (int kb = 0; kb < 4; kb++) {
        const float* ap = &A_g[iload * (T * HK) + jbase + kb * 16 + g * 8];
        float4 v0 = *(const float4*)ap;
        float4 v1 = *(const float4*)(ap + 4);
        As[g * 8 + 0][iload] = v0.x;  As[g * 8 + 1][iload] = v0.y;
        As[g * 8 + 2][iload] = v0.z;  As[g * 8 + 3][iload] = v0.w;
        As[g * 8 + 4][iload] = v1.x;  As[g * 8 + 5][iload] = v1.y;
        As[g * 8 + 6][iload] = v1.z;  As[g * 8 + 7][iload] = v1.w;
        const float4* bp = (const float4*)&M3_g[(jbase + kb * 16) * D];
        ((float4*)Bs)[tid] = bp[tid];
        __syncthreads();
        if (active) {
            #pragma unroll
            for (int hh = 0; hh < 16; hh++) {
                float a[8], b[4];
                #pragma unroll
                for (int r = 0; r < 8; r++) a[r] = As[hh][ty * 8 + r];
                #pragma unroll
                for (int cc = 0; cc < 4; cc++) b[cc] = Bs[hh][tx * 4 + cc];
                #pragma unroll
                for (int r = 0; r < 8; r++)
                    #pragma unroll
                    for (int cc = 0; cc < 4; cc++)
                        acc[r][cc] += a[r] * b[cc];
            }
        }
        __syncthreads();
    }
    float* gp = &Gpart_g[blockIdx.x * (T * D)];
    #pragma unroll
    for (int r = 0; r < 8; r++)
        #pragma unroll
        for (int cc = 0; cc < 4; cc++)
            gp[(ty * 8 + r) * D + tx * 4 + cc] = acc[r][cc];
}

// ------- reduction of partials (full-chip) + bias quadrature term -------
__global__ void kRed(const float* __restrict__ t) {
    __shared__ float red[8][33];
    int b = blockIdx.x;                // 256 blocks, 32 outputs each
    int tid = threadIdx.x;             // 256
    int o = tid & 31, p = tid >> 5;    // p = 0..7
    int idx = b * 32 + o;
    float s = 0.0f;
    #pragma unroll 8
    for (int q = 0; q < 32; q++)
        s += Gpart_g[(p * 32 + q) * (T * D) + idx];
    red[p][o] = s;
    __syncthreads();
    if (p == 0) {
        float acc = red[0][o];
        #pragma unroll
        for (int r = 1; r < 8; r++) acc += red[r][o];
        int i = idx >> 6, d = idx & 63;
        if (i > 0) {
            float dt = t[1] - t[0];
            for (int j = 0; j <= i; j++) {
                float wv = dt;
                if (j == 0) wv *= 0.5f;
                if (j == i) wv *= 0.5f;
                acc += wv * c_g[j * D + d];
            }
        }
        G_g[idx] = acc;
    }
}

// ------- y_new = y0 + w @ G ; write final output on last iteration -------
__global__ void kY(const float* __restrict__ t, const float* __restrict__ z0,
                   float* __restrict__ out, int last) {
    int k = blockIdx.x;                // 128 blocks
    int d = threadIdx.x;               // 64 threads
    float y = z0[d];
    if (k > 0) {
        float dt = t[1] - t[0];
        for (int i = 0; i <= k; i++) {
            float wv = dt;
            if (i == 0) wv *= 0.5f;
            if (i == k) wv *= 0.5f;
            y += wv * G_g[i * D + d];
        }
    }
    Y_g[k * D + d] = y;
    if (last && k == T - 1) out[d] = y;
}

extern "C" void kernel_launch(void* const* d_in, const int* in_sizes, int n_in,
                              void* d_out, int out_size) {
    const float* z0  = (const float*)d_in[0];
    const float* t   = (const float*)d_in[1];
    const float* W1  = (const float*)d_in[2];
    const float* b1  = (const float*)d_in[3];
    const float* W2  = (const float*)d_in[4];
    const float* b2  = (const float*)d_in[5];
    const float* Wk1 = (const float*)d_in[6];
    const float* bk1 = (const float*)d_in[7];
    const float* Wk2 = (const float*)d_in[8];
    const float* bk2 = (const float*)d_in[9];
    float* out = (float*)d_out;

    kInit<<<32, 256>>>(z0);
    kA<<<T, 256>>>(t, Wk1, bk1);
    kT<<<HK, 256>>>(Wk2);
    for (int it = 0; it < ITERS; it++) {
        kF<<<T, 256>>>(W1, b1, W2, b2, bk2);
        kM3<<<HK * 2, 256>>>();
        kG<<<NPART, 256>>>();
        kRed<<<256, 256>>>(t);
        kY<<<T, 64>>>(t, z0, out, (it == ITERS - 1) ? 1 : 0);
    }
}

// round 3
// speedup vs baseline: 1.4705x; 1.1238x over previous
#include <cuda_runtime.h>
#include <math.h>

#define T    128
#define D    64
#define H    256
#define HK   128
#define DD   (D*D)
#define ITERS 3
#define NPART 128   // kG grid: one block per j, full HK per block

// ---- scratch (static device globals; no runtime allocation) ----
__device__ float A_g[T*T*HK];          // 8 MB  A[i][j*HK+h] = w_ij * tanh(...)
__device__ float W2T_g[HK*DD];         // 2 MB  Wk2 transposed per-row: [h][e][d]
__device__ float bk2T_g[DD];           //       bk2 transposed: [e][d]
__device__ float fy_g[T*D];            //       f(y)
__device__ float c_g[T*D];             //       bias projection bk2 . f(y)
__device__ float M3_g[T*HK*D];         // 4 MB  M3[(j*HK+h)][d]
__device__ float Gpart_g[NPART*T*D];   // 4 MB  split-K partials (deterministic)
__device__ float G_g[T*D];
__device__ float Y_g[T*D];

// trapezoid weight w[i][j]: w = dt*(j<=i); w[i,i]*=0.5; w[:,0]*=0.5; w[0,:]=0
__device__ __forceinline__ float wfun(int i, int j, float dt) {
    if (i == 0 || j > i) return 0.0f;
    float v = dt;
    if (j == i) v *= 0.5f;
    if (j == 0) v *= 0.5f;
    return v;
}

// ---------------- init: Y = tile(y0) ----------------
__global__ void kInit(const float* __restrict__ z0) {
    int idx = blockIdx.x * 256 + threadIdx.x;      // 8192
    Y_g[idx] = z0[idx & (D - 1)];
}

// ------- A[i][j*HK+h] = w_ij * tanh(t_i*Wk1[0,h] + t_j*Wk1[1,h] + bk1[h]) -------
__global__ void kA(const float* __restrict__ t, const float* __restrict__ Wk1,
                   const float* __restrict__ bk1) {
    __shared__ float wa[HK], wb[HK], bk[HK], ts[T];
    int tid = threadIdx.x;
    int i = blockIdx.x;
    if (tid < HK) { wa[tid] = Wk1[tid]; wb[tid] = Wk1[HK + tid]; bk[tid] = bk1[tid]; }
    if (tid < T)  ts[tid] = t[tid];
    __syncthreads();
    float ti = ts[i];
    float dt = ts[1] - ts[0];
    #pragma unroll 4
    for (int r = 0; r < 64; r++) {
        int idx = tid + r * 256;                  // 0..16383
        int j = idx >> 7, h = idx & 127;
        float v = tanhf(ti * wa[h] + ts[j] * wb[h] + bk[h]);
        A_g[i * (T * HK) + idx] = wfun(i, j, dt) * v;
    }
}

// ------- one-time transpose: W2T[h][e][d] = Wk2[h][d*64+e] -------
__global__ void kT(const float* __restrict__ Wk2) {
    __shared__ float sm[D * 67];
    int h = blockIdx.x;            // 128 blocks
    int tid = threadIdx.x;         // 256
    #pragma unroll
    for (int r = 0; r < 16; r++) {
        int idx = tid + r * 256;   // d = idx>>6, e = idx&63
        sm[(idx >> 6) * 67 + (idx & 63)] = Wk2[h * DD + idx];
    }
    __syncthreads();
    #pragma unroll
    for (int r = 0; r < 16; r++) {
        int idx = tid + r * 256;   // e = idx>>6, d = idx&63
        W2T_g[h * DD + idx] = sm[(idx & 63) * 67 + (idx >> 6)];
    }
}

// ------- one-time transpose: bk2T[e][d] = bk2[d*64+e] -------
__global__ void kTb(const float* __restrict__ bk2) {
    __shared__ float sm[D * 67];
    int tid = threadIdx.x;         // 256, single block
    #pragma unroll
    for (int r = 0; r < 16; r++) {
        int idx = tid + r * 256;
        sm[(idx >> 6) * 67 + (idx & 63)] = bk2[idx];
    }
    __syncthreads();
    #pragma unroll
    for (int r = 0; r < 16; r++) {
        int idx = tid + r * 256;
        bk2T_g[idx] = sm[(idx & 63) * 67 + (idx >> 6)];
    }
}

// ------- f(y) = tanh(y W1 + b1) W2 + b2 ; c = bk2T^T applied to f(y) -------
// All 256 threads active in every phase; coalesced loads; 4-way split-K + smem reduce.
__global__ void kF(const float* __restrict__ W1, const float* __restrict__ b1,
                   const float* __restrict__ W2, const float* __restrict__ b2) {
    __shared__ float yrow[D];
    __shared__ float hid[H];
    __shared__ float fyr[D];
    __shared__ float part[4][D];
    int j = blockIdx.x;            // 128 blocks
    int tid = threadIdx.x;         // 256 threads
    if (tid < D) yrow[tid] = Y_g[j * D + tid];
    __syncthreads();
    // hidden: one h per thread, coalesced W1 columns, full unroll (high MLP)
    {
        float s = b1[tid];
        #pragma unroll
        for (int e = 0; e < D; e++) s += yrow[e] * W1[e * H + tid];
        hid[tid] = tanhf(s);
    }
    __syncthreads();
    int d = tid & 63;
    int p = tid >> 6;              // 4-way split
    // fy: thread (d,p) sums h in [64p, 64p+64), W2[h*D+d] coalesced in d
    {
        float s = 0.0f;
        #pragma unroll
        for (int hh = 0; hh < 64; hh++) {
            int h = p * 64 + hh;
            s += hid[h] * W2[h * D + d];
        }
        part[p][d] = s;
    }
    __syncthreads();
    if (p == 0) {
        float f = b2[d] + part[0][d] + part[1][d] + part[2][d] + part[3][d];
        fyr[d] = f;
        fy_g[j * D + d] = f;
    }
    __syncthreads();
    // c: thread (d,p) sums e in [16p, 16p+16), bk2T[e*D+d] coalesced in d
    {
        float s = 0.0f;
        #pragma unroll
        for (int ee = 0; ee < 16; ee++) {
            int e = p * 16 + ee;
            s += bk2T_g[e * D + d] * fyr[e];
        }
        part[p][d] = s;
    }
    __syncthreads();
    if (p == 0)
        c_g[j * D + d] = part[0][d] + part[1][d] + part[2][d] + part[3][d];
}

// ------- M3[(j*HK+h)][d] = sum_e W2T[h][e][d] * fy[j,e] -------
__global__ void kM3() {
    __shared__ float w2s[D * D];       // [e][d] raw, conflict-free
    __shared__ float fys[D * 65];      // [j][e] padded
    int h  = blockIdx.x >> 1;          // 128
    int jh = blockIdx.x & 1;           // j half
    int tid = threadIdx.x;             // 256
    #pragma unroll
    for (int r = 0; r < 16; r++)
        w2s[tid + r * 256] = W2T_g[h * DD + tid + r * 256];
    #pragma unroll
    for (int r = 0; r < 16; r++) {
        int idx = tid + r * 256;       // j = idx>>6, e = idx&63
        fys[(idx >> 6) * 65 + (idx & 63)] = fy_g[jh * 64 * D + idx];
    }
    __syncthreads();
    int tx = tid & 15;                 // d-chunk: 4*tx
    int ty = tid >> 4;                 // j-chunk: 4*ty
    float acc[4][4] = {};
    #pragma unroll
    for (int e = 0; e < D; e++) {
        float4 wv = *(const float4*)&w2s[e * 64 + tx * 4];
        #pragma unroll
        for (int jl = 0; jl < 4; jl++) {
            float f = fys[(ty * 4 + jl) * 65 + e];
            acc[jl][0] += f * wv.x; acc[jl][1] += f * wv.y;
            acc[jl][2] += f * wv.z; acc[jl][3] += f * wv.w;
        }
    }
    #pragma unroll
    for (int jl = 0; jl < 4; jl++) {
        int j = jh * 64 + ty * 4 + jl;
        float4 o = make_float4(acc[jl][0], acc[jl][1], acc[jl][2], acc[jl][3]);
        *(float4*)&M3_g[(j * HK + h) * D + tx * 4] = o;
    }
}

// ------- split-K GEMM: Gpart[j][i][d] = sum_{h=0..127} A[i][j*HK+h] * M3[(j,h)][d] -------
__global__ void kG() {
    __shared__ float As[16][T];    // [hh][i]
    __shared__ float Bs[16][D];    // [hh][d]
    int j   = blockIdx.x;          // 128 blocks
    int tid = threadIdx.x;
    int tx = tid & 15;             // d cols tx*4..+3
    int ty = tid >> 4;             // i rows ty*8..+7
    float acc[8][4] = {};
    bool active = (ty * 8 + 7) >= j;
    int jbase = j * HK;
    int iload = tid >> 1;          // 0..127
    int g = tid & 1;
    #pragma unroll
    for (int kb = 0; kb < 8; kb++) {
        const float* ap = &A_g[iload * (T * HK) + jbase + kb * 16 + g * 8];
        float4 v0 = *(const float4*)ap;
        float4 v1 = *(const float4*)(ap + 4);
        As[g * 8 + 0][iload] = v0.x;  As[g * 8 + 1][iload] = v0.y;
        As[g * 8 + 2][iload] = v0.z;  As[g * 8 + 3][iload] = v0.w;
        As[g * 8 + 4][iload] = v1.x;  As[g * 8 + 5][iload] = v1.y;
        As[g * 8 + 6][iload] = v1.z;  As[g * 8 + 7][iload] = v1.w;
        const float4* bp = (const float4*)&M3_g[(jbase + kb * 16) * D];
        ((float4*)Bs)[tid] = bp[tid];
        __syncthreads();
        if (active) {
            #pragma unroll
            for (int hh = 0; hh < 16; hh++) {
                float a[8], b[4];
                #pragma unroll
                for (int r = 0; r < 8; r++) a[r] = As[hh][ty * 8 + r];
                #pragma unroll
                for (int cc = 0; cc < 4; cc++) b[cc] = Bs[hh][tx * 4 + cc];
                #pragma unroll
                for (int r = 0; r < 8; r++)
                    #pragma unroll
                    for (int cc = 0; cc < 4; cc++)
                        acc[r][cc] += a[r] * b[cc];
            }
        }
        __syncthreads();
    }
    float* gp = &Gpart_g[j * (T * D)];
    #pragma unroll
    for (int r = 0; r < 8; r++)
        #pragma unroll
        for (int cc = 0; cc < 4; cc++)
            gp[(ty * 8 + r) * D + tx * 4 + cc] = acc[r][cc];
}

// ------- reduction of 128 partials (full-chip) + bias quadrature term -------
__global__ void kRed(const float* __restrict__ t) {
    __shared__ float red[8][33];
    int b = blockIdx.x;                // 256 blocks, 32 outputs each
    int tid = threadIdx.x;             // 256
    int o = tid & 31, p = tid >> 5;    // p = 0..7
    int idx = b * 32 + o;
    float s = 0.0f;
    #pragma unroll 4
    for (int q = 0; q < 16; q++)
        s += Gpart_g[(p * 16 + q) * (T * D) + idx];
    red[p][o] = s;
    __syncthreads();
    if (p == 0) {
        float acc = red[0][o];
        #pragma unroll
        for (int r = 1; r < 8; r++) acc += red[r][o];
        int i = idx >> 6, d = idx & 63;
        if (i > 0) {
            float dt = t[1] - t[0];
            for (int j = 0; j <= i; j++) {
                float wv = dt;
                if (j == 0) wv *= 0.5f;
                if (j == i) wv *= 0.5f;
                acc += wv * c_g[j * D + d];
            }
        }
        G_g[idx] = acc;
    }
}

// ------- y_new = y0 + w @ G ; write final output on last iteration -------
__global__ void kY(const float* __restrict__ t, const float* __restrict__ z0,
                   float* __restrict__ out, int last) {
    int k = blockIdx.x;                // 128 blocks
    int d = threadIdx.x;               // 64 threads
    float y = z0[d];
    if (k > 0) {
        float dt = t[1] - t[0];
        for (int i = 0; i <= k; i++) {
            float wv = dt;
            if (i == 0) wv *= 0.5f;
            if (i == k) wv *= 0.5f;
            y += wv * G_g[i * D + d];
        }
    }
    Y_g[k * D + d] = y;
    if (last && k == T - 1) out[d] = y;
}

extern "C" void kernel_launch(void* const* d_in, const int* in_sizes, int n_in,
                              void* d_out, int out_size) {
    const float* z0  = (const float*)d_in[0];
    const float* t   = (const float*)d_in[1];
    const float* W1  = (const float*)d_in[2];
    const float* b1  = (const float*)d_in[3];
    const float* W2  = (const float*)d_in[4];
    const float* b2  = (const float*)d_in[5];
    const float* Wk1 = (const float*)d_in[6];
    const float* bk1 = (const float*)d_in[7];
    const float* Wk2 = (const float*)d_in[8];
    const float* bk2 = (const float*)d_in[9];
    float* out = (float*)d_out;

    kInit<<<32, 256>>>(z0);
    kA<<<T, 256>>>(t, Wk1, bk1);
    kT<<<HK, 256>>>(Wk2);
    kTb<<<1, 256>>>(bk2);
    for (int it = 0; it < ITERS; it++) {
        kF<<<T, 256>>>(W1, b1, W2, b2);
        kM3<<<HK * 2, 256>>>();
        kG<<<NPART, 256>>>();
        kRed<<<256, 256>>>(t);
        kY<<<T, 64>>>(t, z0, out, (it == ITERS - 1) ? 1 : 0);
    }
}

// round 4
// speedup vs baseline: 1.7464x; 1.1877x over previous
#include <cuda_runtime.h>
#include <math.h>

#define T    128
#define D    64
#define H    256
#define HK   128
#define DD   (D*D)
#define ITERS 3
#define NB   128
#define NT   256

// ---- scratch (static device globals; no runtime allocation) ----
__device__ float A_g[T*T*HK];          // 8 MB  A[i][j*HK+h] = w_ij * tanh(...)
__device__ float W2T_g[HK*DD];         // 2 MB  Wk2 transposed per-row: [h][e][d]
__device__ float bk2T_g[DD];           //       bk2 transposed: [e][d]
__device__ float fy_g[T*D];
__device__ float c_g[T*D];
__device__ float M3_g[T*HK*D];         // 4 MB
__device__ float Gpart_g[NB*T*D];      // 4 MB
__device__ float G_g[T*D];
__device__ float Y_g[T*D];

// grid barrier state: arrive/depart pair per instance; last departer resets both,
// so every launch (and every graph replay) starts from zeroed counters.
__device__ unsigned bar_arr[16];
__device__ unsigned bar_dep[16];

__device__ __forceinline__ void gsync(int b) {
    __threadfence();
    __syncthreads();
    if (threadIdx.x == 0) {
        atomicAdd(&bar_arr[b], 1u);
        while (*(volatile unsigned*)&bar_arr[b] < NB) { __nanosleep(20); }
        __threadfence();
        unsigned o = atomicAdd(&bar_dep[b], 1u);
        if (o == NB - 1) {
            *(volatile unsigned*)&bar_arr[b] = 0u;
            *(volatile unsigned*)&bar_dep[b] = 0u;
        }
    }
    __syncthreads();
}

// trapezoid weight w[i][j]: w = dt*(j<=i); w[i,i]*=0.5; w[:,0]*=0.5; w[0,:]=0
__device__ __forceinline__ float wfun(int i, int j, float dt) {
    if (i == 0 || j > i) return 0.0f;
    float v = dt;
    if (j == i) v *= 0.5f;
    if (j == 0) v *= 0.5f;
    return v;
}

__global__ void __launch_bounds__(NT, 1) mega(
    const float* __restrict__ z0, const float* __restrict__ t,
    const float* __restrict__ W1, const float* __restrict__ b1,
    const float* __restrict__ W2, const float* __restrict__ b2,
    const float* __restrict__ Wk1, const float* __restrict__ bk1,
    const float* __restrict__ Wk2, const float* __restrict__ bk2,
    float* __restrict__ out)
{
    __shared__ float sbuf[8256];                 // 33 KB multipurpose
    __shared__ float wa[HK], wb[HK], bkk[HK], ts[T];
    __shared__ float yrow[D], hid[H], fyr[D], part[4][D];

    int bid = blockIdx.x, tid = threadIdx.x;

    // ================= SETUP (one pass) =================
    // W2T[h=bid][e][d] = Wk2[h][d*64+e], via padded smem transpose
    #pragma unroll
    for (int r = 0; r < 16; r++) {
        int idx = tid + r * 256;
        sbuf[(idx >> 6) * 67 + (idx & 63)] = Wk2[bid * DD + idx];
    }
    __syncthreads();
    #pragma unroll
    for (int r = 0; r < 16; r++) {
        int idx = tid + r * 256;
        W2T_g[bid * DD + idx] = sbuf[(idx & 63) * 67 + (idx >> 6)];
    }
    __syncthreads();
    if (bid == 0) {   // bk2T (block 0 only; block-uniform branch, syncthreads legal)
        #pragma unroll
        for (int r = 0; r < 16; r++) {
            int idx = tid + r * 256;
            sbuf[(idx >> 6) * 67 + (idx & 63)] = bk2[idx];
        }
        __syncthreads();
        #pragma unroll
        for (int r = 0; r < 16; r++) {
            int idx = tid + r * 256;
            bk2T_g[idx] = sbuf[(idx & 63) * 67 + (idx >> 6)];
        }
    }
    // A row i = bid
    if (tid < HK) { wa[tid] = Wk1[tid]; wb[tid] = Wk1[HK + tid]; bkk[tid] = bk1[tid]; }
    if (tid < T)  ts[tid] = t[tid];
    __syncthreads();
    float dt = ts[1] - ts[0];
    {
        float ti = ts[bid];
        #pragma unroll 4
        for (int r = 0; r < 64; r++) {
            int idx = tid + r * 256;
            int j = idx >> 7, h = idx & 127;
            float v = tanhf(ti * wa[h] + ts[j] * wb[h] + bkk[h]);
            A_g[bid * (T * HK) + idx] = wfun(bid, j, dt) * v;
        }
    }
    if (tid < D) Y_g[bid * D + tid] = z0[tid];

    int bar = 0;
    gsync(bar++);

    // ================= FIXED-POINT ITERATIONS =================
    for (int it = 0; it < ITERS; it++) {
        // ---- phase F: block j computes fy[j], c[j] ----
        {
            int j = bid;
            if (tid < D) yrow[tid] = __ldcg(&Y_g[j * D + tid]);
            __syncthreads();
            float s = b1[tid];
            #pragma unroll
            for (int e = 0; e < D; e++) s += yrow[e] * W1[e * H + tid];
            hid[tid] = tanhf(s);
            __syncthreads();
            int d = tid & 63, p = tid >> 6;
            float s2 = 0.0f;
            #pragma unroll
            for (int hh = 0; hh < 64; hh++) { int h = p * 64 + hh; s2 += hid[h] * W2[h * D + d]; }
            part[p][d] = s2;
            __syncthreads();
            if (p == 0) {
                float f = b2[d] + part[0][d] + part[1][d] + part[2][d] + part[3][d];
                fyr[d] = f;
                fy_g[j * D + d] = f;
            }
            __syncthreads();
            float s3 = 0.0f;
            #pragma unroll
            for (int ee = 0; ee < 16; ee++) { int e = p * 16 + ee; s3 += bk2T_g[e * D + d] * fyr[e]; }
            part[p][d] = s3;
            __syncthreads();
            if (p == 0) c_g[j * D + d] = part[0][d] + part[1][d] + part[2][d] + part[3][d];
        }
        gsync(bar++);

        // ---- phase M3: block h computes M3[(j,h)][d], two j-halves ----
        {
            int h = bid;
            float* w2s = sbuf;           // [e][d] 4096
            float* fys = sbuf + 4096;    // [jl][e] padded 65
            #pragma unroll
            for (int r = 0; r < 16; r++)
                w2s[tid + r * 256] = W2T_g[h * DD + tid + r * 256];
            for (int jh = 0; jh < 2; jh++) {
                __syncthreads();
                #pragma unroll
                for (int r = 0; r < 16; r++) {
                    int idx = tid + r * 256;
                    fys[(idx >> 6) * 65 + (idx & 63)] = __ldcg(&fy_g[jh * 64 * D + idx]);
                }
                __syncthreads();
                int tx = tid & 15, ty = tid >> 4;
                float acc[4][4] = {};
                #pragma unroll
                for (int e = 0; e < D; e++) {
                    float4 wv = *(const float4*)&w2s[e * 64 + tx * 4];
                    #pragma unroll
                    for (int jl = 0; jl < 4; jl++) {
                        float f = fys[(ty * 4 + jl) * 65 + e];
                        acc[jl][0] += f * wv.x; acc[jl][1] += f * wv.y;
                        acc[jl][2] += f * wv.z; acc[jl][3] += f * wv.w;
                    }
                }
                #pragma unroll
                for (int jl = 0; jl < 4; jl++) {
                    int j = jh * 64 + ty * 4 + jl;
                    float4 o = make_float4(acc[jl][0], acc[jl][1], acc[jl][2], acc[jl][3]);
                    __stcg((float4*)&M3_g[(j * HK + h) * D + tx * 4], o);
                }
            }
        }
        gsync(bar++);

        // ---- phase G: block b runs (j=b, h-half0) + (j=127-b, h-half1) into one acc ----
        // row-chunk map pairs low/high rows on the same SMSP for triangular balance
        {
            float* As = sbuf;            // [hh][i] 16x128
            float* Bs = sbuf + 2048;     // [hh][d] 16x64
            int tx = tid & 15, ty = tid >> 4;
            int w = ty >> 1;
            int chunk = (w < 4) ? w : (11 - w);          // 0,1,2,3,7,6,5,4
            int rbase = chunk * 16 + (ty & 1) * 8;
            float acc[8][4] = {};
            int iload = tid >> 1, g = tid & 1;
            #pragma unroll
            for (int task = 0; task < 2; task++) {
                int j = task ? (127 - bid) : bid;
                int jbase = j * HK + task * 64;
                bool active = (rbase + 7) >= j;
                #pragma unroll
                for (int kb = 0; kb < 4; kb++) {
                    __syncthreads();
                    const float* ap = &A_g[iload * (T * HK) + jbase + kb * 16 + g * 8];
                    float4 v0 = *(const float4*)ap;
                    float4 v1 = *(const float4*)(ap + 4);
                    As[(g * 8 + 0) * 128 + iload] = v0.x;  As[(g * 8 + 1) * 128 + iload] = v0.y;
                    As[(g * 8 + 2) * 128 + iload] = v0.z;  As[(g * 8 + 3) * 128 + iload] = v0.w;
                    As[(g * 8 + 4) * 128 + iload] = v1.x;  As[(g * 8 + 5) * 128 + iload] = v1.y;
                    As[(g * 8 + 6) * 128 + iload] = v1.z;  As[(g * 8 + 7) * 128 + iload] = v1.w;
                    ((float4*)Bs)[tid] = __ldcg(((const float4*)&M3_g[(jbase + kb * 16) * D]) + tid);
                    __syncthreads();
                    if (active) {
                        #pragma unroll
                        for (int hh = 0; hh < 16; hh++) {
                            float a[8], b[4];
                            #pragma unroll
                            for (int r = 0; r < 8; r++) a[r] = As[hh * 128 + rbase + r];
                            #pragma unroll
                            for (int cc = 0; cc < 4; cc++) b[cc] = Bs[hh * 64 + tx * 4 + cc];
                            #pragma unroll
                            for (int r = 0; r < 8; r++)
                                #pragma unroll
                                for (int cc = 0; cc < 4; cc++)
                                    acc[r][cc] += a[r] * b[cc];
                        }
                    }
                }
            }
            float* gp = &Gpart_g[bid * (T * D)];
            #pragma unroll
            for (int r = 0; r < 8; r++) {
                float4 o = make_float4(acc[r][0], acc[r][1], acc[r][2], acc[r][3]);
                *(float4*)&gp[(rbase + r) * D + tx * 4] = o;
            }
        }
        gsync(bar++);

        // ---- phase R: block i reduces 128 partials + bias quadrature ----
        {
            int i = bid;
            int d = tid & 63, p = tid >> 6;
            float s = 0.0f;
            #pragma unroll 8
            for (int slot = p; slot < NB; slot += 4)
                s += __ldcg(&Gpart_g[slot * (T * D) + i * D + d]);
            for (int j = p; j <= i; j += 4)
                s += wfun(i, j, dt) * __ldcg(&c_g[j * D + d]);
            part[p][d] = s;
            __syncthreads();
            if (p == 0)
                G_g[i * D + d] = part[0][d] + part[1][d] + part[2][d] + part[3][d];
        }
        gsync(bar++);

        // ---- phase Y: block k computes y[k] = y0 + (w @ G)[k] ----
        {
            int k = bid;
            int d = tid & 63, p = tid >> 6;
            float s = 0.0f;
            for (int i2 = p; i2 <= k; i2 += 4)
                s += wfun(k, i2, dt) * __ldcg(&G_g[i2 * D + d]);
            part[p][d] = s;
            __syncthreads();
            if (p == 0) {
                float y = z0[d] + part[0][d] + part[1][d] + part[2][d] + part[3][d];
                Y_g[k * D + d] = y;
                if (it == ITERS - 1 && k == T - 1) out[d] = y;
            }
        }
        if (it < ITERS - 1) gsync(bar++);
    }
}

extern "C" void kernel_launch(void* const* d_in, const int* in_sizes, int n_in,
                              void* d_out, int out_size) {
    const float* z0  = (const float*)d_in[0];
    const float* t   = (const float*)d_in[1];
    const float* W1  = (const float*)d_in[2];
    const float* b1  = (const float*)d_in[3];
    const float* W2  = (const float*)d_in[4];
    const float* b2  = (const float*)d_in[5];
    const float* Wk1 = (const float*)d_in[6];
    const float* bk1 = (const float*)d_in[7];
    const float* Wk2 = (const float*)d_in[8];
    const float* bk2 = (const float*)d_in[9];
    float* out = (float*)d_out;

    mega<<<NB, NT>>>(z0, t, W1, b1, W2, b2, Wk1, bk1, Wk2, bk2, out);
}

// round 5
// speedup vs baseline: 1.8075x; 1.0349x over previous
#include <cuda_runtime.h>
#include <math.h>

#define T    128
#define D    64
#define H    256
#define HK   128
#define DD   (D*D)
#define ITERS 3
#define NB   128
#define NT   512

// ---- scratch (static device globals; no runtime allocation) ----
__device__ float A_g[T*T*HK];          // 8 MB  A[i][j*HK+h] = w_ij * tanh(...)
__device__ float W2T_g[HK*DD];         // 2 MB  Wk2 transposed per-row: [h][e][d]
__device__ float bk2T_g[DD];           //       bk2 transposed: [e][d]
__device__ float fy_g[T*D];
__device__ float c_g[T*D];
__device__ float M3_g[T*HK*D];         // 4 MB
__device__ float Gpart_g[NB*T*D];      // 4 MB
__device__ float G_g[T*D];

// grid barrier: arrive/depart pair per instance; last departer resets both,
// so every launch / graph replay starts from zeroed counters.
__device__ unsigned bar_arr[16];
__device__ unsigned bar_dep[16];

__device__ __forceinline__ void gsync(int b) {
    __threadfence();
    __syncthreads();
    if (threadIdx.x == 0) {
        atomicAdd(&bar_arr[b], 1u);
        while (*(volatile unsigned*)&bar_arr[b] < NB) { }
        __threadfence();
        unsigned o = atomicAdd(&bar_dep[b], 1u);
        if (o == NB - 1) {
            *(volatile unsigned*)&bar_arr[b] = 0u;
            *(volatile unsigned*)&bar_dep[b] = 0u;
        }
    }
    __syncthreads();
}

// trapezoid weight w[i][j]: w = dt*(j<=i); w[i,i]*=0.5; w[:,0]*=0.5; w[0,:]=0
__device__ __forceinline__ float wfun(int i, int j, float dt) {
    if (i == 0 || j > i) return 0.0f;
    float v = dt;
    if (j == i) v *= 0.5f;
    if (j == 0) v *= 0.5f;
    return v;
}

__global__ void __launch_bounds__(NT, 1) mega(
    const float* __restrict__ z0, const float* __restrict__ t,
    const float* __restrict__ W1, const float* __restrict__ b1,
    const float* __restrict__ W2, const float* __restrict__ b2,
    const float* __restrict__ Wk1, const float* __restrict__ bk1,
    const float* __restrict__ Wk2, const float* __restrict__ bk2,
    float* __restrict__ out)
{
    __shared__ float sbuf[8256];                 // 33 KB multipurpose
    __shared__ float wa[HK], wb[HK], bkk[HK], ts[T];
    __shared__ float yrow[D], hid[H], fyr[D];
    __shared__ float part8[8][D];
    __shared__ float hidpart[2][H];

    int bid = blockIdx.x, tid = threadIdx.x;

    // ================= SETUP =================
    // W2T[h=bid][e][d] = Wk2[h][d*64+e]
    #pragma unroll
    for (int r = 0; r < 8; r++) {
        int idx = tid + r * 512;
        sbuf[(idx >> 6) * 67 + (idx & 63)] = Wk2[bid * DD + idx];
    }
    __syncthreads();
    #pragma unroll
    for (int r = 0; r < 8; r++) {
        int idx = tid + r * 512;
        W2T_g[bid * DD + idx] = sbuf[(idx & 63) * 67 + (idx >> 6)];
    }
    __syncthreads();
    if (bid == 0) {            // bk2T (block-uniform branch; syncthreads legal)
        #pragma unroll
        for (int r = 0; r < 8; r++) {
            int idx = tid + r * 512;
            sbuf[(idx >> 6) * 67 + (idx & 63)] = bk2[idx];
        }
        __syncthreads();
        #pragma unroll
        for (int r = 0; r < 8; r++) {
            int idx = tid + r * 512;
            bk2T_g[idx] = sbuf[(idx & 63) * 67 + (idx >> 6)];
        }
    }
    if (tid < HK) { wa[tid] = Wk1[tid]; wb[tid] = Wk1[HK + tid]; bkk[tid] = bk1[tid]; }
    if (tid < T)  ts[tid] = t[tid];
    __syncthreads();
    float dt = ts[1] - ts[0];
    {
        float ti = ts[bid];
        #pragma unroll 4
        for (int r = 0; r < 32; r++) {
            int idx = tid + r * 512;
            int j = idx >> 7, h = idx & 127;
            float v = tanhf(ti * wa[h] + ts[j] * wb[h] + bkk[h]);
            A_g[bid * (T * HK) + idx] = wfun(bid, j, dt) * v;
        }
    }

    int bar = 0;
    gsync(bar++);

    // ================= FIXED-POINT ITERATIONS =================
    for (int it = 0; it < ITERS; it++) {
        // ---- phase F (block j): y_j = y0 + (w@G)_j (fused), then fy[j], c[j] ----
        {
            int j = bid;
            int d = tid & 63, p = tid >> 6;        // 8-way split
            if (it == 0) {
                if (tid < D) yrow[tid] = z0[tid];
            } else {
                float s = 0.0f;
                for (int i = p; i <= j; i += 8)
                    s += wfun(j, i, dt) * __ldcg(&G_g[i * D + d]);
                part8[p][d] = s;
                __syncthreads();
                if (p == 0)
                    yrow[d] = z0[d] + part8[0][d] + part8[1][d] + part8[2][d] + part8[3][d]
                                    + part8[4][d] + part8[5][d] + part8[6][d] + part8[7][d];
            }
            __syncthreads();
            // hidden: (h, q) q=2-way split over e
            {
                int h = tid & 255, q = tid >> 8;
                float s = (q == 0) ? b1[h] : 0.0f;
                #pragma unroll
                for (int ee = 0; ee < 32; ee++) {
                    int e = q * 32 + ee;
                    s += yrow[e] * W1[e * H + h];
                }
                hidpart[q][h] = s;
            }
            __syncthreads();
            if (tid < H) hid[tid] = tanhf(hidpart[0][tid] + hidpart[1][tid]);
            __syncthreads();
            // fy: 8-way split over h (32 each)
            {
                float s = 0.0f;
                #pragma unroll
                for (int hh = 0; hh < 32; hh++) {
                    int h = p * 32 + hh;
                    s += hid[h] * W2[h * D + d];
                }
                part8[p][d] = s;
            }
            __syncthreads();
            if (p == 0) {
                float f = b2[d] + part8[0][d] + part8[1][d] + part8[2][d] + part8[3][d]
                                + part8[4][d] + part8[5][d] + part8[6][d] + part8[7][d];
                fyr[d] = f;
                fy_g[j * D + d] = f;
            }
            __syncthreads();
            // c: 8-way split over e (8 each)
            {
                float s = 0.0f;
                #pragma unroll
                for (int ee = 0; ee < 8; ee++) {
                    int e = p * 8 + ee;
                    s += bk2T_g[e * D + d] * fyr[e];
                }
                part8[p][d] = s;
            }
            __syncthreads();
            if (p == 0)
                c_g[j * D + d] = part8[0][d] + part8[1][d] + part8[2][d] + part8[3][d]
                               + part8[4][d] + part8[5][d] + part8[6][d] + part8[7][d];
        }
        gsync(bar++);

        // ---- phase M3 (block h): M3[(j,h)][d], two j-halves ----
        {
            int h = bid;
            float* w2s = sbuf;           // [e][d] 4096
            float* fys = sbuf + 4096;    // [jl][e] padded 65
            #pragma unroll
            for (int r = 0; r < 8; r++)
                w2s[tid + r * 512] = W2T_g[h * DD + tid + r * 512];
            for (int jh = 0; jh < 2; jh++) {
                __syncthreads();
                #pragma unroll
                for (int r = 0; r < 8; r++) {
                    int idx = tid + r * 512;
                    fys[(idx >> 6) * 65 + (idx & 63)] = __ldcg(&fy_g[jh * 64 * D + idx]);
                }
                __syncthreads();
                int tx = tid & 15, ty = tid >> 4;          // ty 0..31, 2 j each
                float acc[2][4] = {};
                #pragma unroll
                for (int e = 0; e < D; e++) {
                    float4 wv = *(const float4*)&w2s[e * 64 + tx * 4];
                    #pragma unroll
                    for (int jl = 0; jl < 2; jl++) {
                        float f = fys[(ty * 2 + jl) * 65 + e];
                        acc[jl][0] += f * wv.x; acc[jl][1] += f * wv.y;
                        acc[jl][2] += f * wv.z; acc[jl][3] += f * wv.w;
                    }
                }
                #pragma unroll
                for (int jl = 0; jl < 2; jl++) {
                    int j = jh * 64 + ty * 2 + jl;
                    float4 o = make_float4(acc[jl][0], acc[jl][1], acc[jl][2], acc[jl][3]);
                    __stcg((float4*)&M3_g[(j * HK + h) * D + tx * 4], o);
                }
            }
        }
        gsync(bar++);

        // ---- phase G (block b): tasks (j=b, h-half0) + (j=127-b, h-half1) ----
        {
            float* As = sbuf;            // [hh][i] 16x128
            float* Bs = sbuf + 2048;     // [hh][d] 16x64
            int tx = tid & 15, ty = tid >> 4;   // ty 0..31 -> rows ty*4..+3
            float acc[4][4] = {};
            int iload = tid >> 2, g4 = tid & 3;
            #pragma unroll
            for (int task = 0; task < 2; task++) {
                int j = task ? (127 - bid) : bid;
                int jbase = j * HK + task * 64;
                bool active = (ty * 4 + 3) >= j;
                #pragma unroll
                for (int kb = 0; kb < 4; kb++) {
                    __syncthreads();
                    const float* ap = &A_g[iload * (T * HK) + jbase + kb * 16 + g4 * 4];
                    float4 v = *(const float4*)ap;
                    As[(g4 * 4 + 0) * 128 + iload] = v.x;
                    As[(g4 * 4 + 1) * 128 + iload] = v.y;
                    As[(g4 * 4 + 2) * 128 + iload] = v.z;
                    As[(g4 * 4 + 3) * 128 + iload] = v.w;
                    ((float2*)Bs)[tid] = __ldcg(((const float2*)&M3_g[(jbase + kb * 16) * D]) + tid);
                    __syncthreads();
                    if (active) {
                        #pragma unroll
                        for (int hh = 0; hh < 16; hh++) {
                            float a[4], b[4];
                            #pragma unroll
                            for (int r = 0; r < 4; r++) a[r] = As[hh * 128 + ty * 4 + r];
                            #pragma unroll
                            for (int cc = 0; cc < 4; cc++) b[cc] = Bs[hh * 64 + tx * 4 + cc];
                            #pragma unroll
                            for (int r = 0; r < 4; r++)
                                #pragma unroll
                                for (int cc = 0; cc < 4; cc++)
                                    acc[r][cc] += a[r] * b[cc];
                        }
                    }
                }
            }
            float* gp = &Gpart_g[bid * (T * D)];
            #pragma unroll
            for (int r = 0; r < 4; r++) {
                float4 o = make_float4(acc[r][0], acc[r][1], acc[r][2], acc[r][3]);
                *(float4*)&gp[(ty * 4 + r) * D + tx * 4] = o;
            }
        }
        gsync(bar++);

        // ---- phase R (block i): reduce 128 partials + bias quadrature -> G ----
        {
            int i = bid;
            int d = tid & 63, p = tid >> 6;
            float s = 0.0f;
            #pragma unroll 4
            for (int slot = p; slot < NB; slot += 8)
                s += __ldcg(&Gpart_g[slot * (T * D) + i * D + d]);
            for (int j = p; j <= i; j += 8)
                s += wfun(i, j, dt) * __ldcg(&c_g[j * D + d]);
            part8[p][d] = s;
            __syncthreads();
            if (p == 0)
                G_g[i * D + d] = part8[0][d] + part8[1][d] + part8[2][d] + part8[3][d]
                               + part8[4][d] + part8[5][d] + part8[6][d] + part8[7][d];
        }
        gsync(bar++);
    }

    // ---- tail: block 127 computes out = y0 + (w@G)_{127} ----
    if (bid == T - 1) {
        int d = tid & 63, p = tid >> 6;
        float s = 0.0f;
        for (int i = p; i < T; i += 8)
            s += wfun(T - 1, i, dt) * __ldcg(&G_g[i * D + d]);
        part8[p][d] = s;
        __syncthreads();
        if (p == 0)
            out[d] = z0[d] + part8[0][d] + part8[1][d] + part8[2][d] + part8[3][d]
                           + part8[4][d] + part8[5][d] + part8[6][d] + part8[7][d];
    }
}

extern "C" void kernel_launch(void* const* d_in, const int* in_sizes, int n_in,
                              void* d_out, int out_size) {
    const float* z0  = (const float*)d_in[0];
    const float* t   = (const float*)d_in[1];
    const float* W1  = (const float*)d_in[2];
    const float* b1  = (const float*)d_in[3];
    const float* W2  = (const float*)d_in[4];
    const float* b2  = (const float*)d_in[5];
    const float* Wk1 = (const float*)d_in[6];
    const float* bk1 = (const float*)d_in[7];
    const float* Wk2 = (const float*)d_in[8];
    const float* bk2 = (const float*)d_in[9];
    float* out = (float*)d_out;

    mega<<<NB, NT>>>(z0, t, W1, b1, W2, b2, Wk1, bk1, Wk2, bk2, out);
}